// round 6
// baseline (speedup 1.0000x reference)
#include <cuda_runtime.h>
#include <cuda_bf16.h>

// LengthRegulator: expand x[b,s,:] by duration[b,s] along time, then mask.
// out layout: [B*max_mel*E] floats, then [B*max_mel] mask floats (0.0/1.0).

#define B_CONST 32
#define S_CONST 1024

__device__ int g_cum[B_CONST * S_CONST];
__device__ int g_mel[B_CONST];

__global__ void cumsum_kernel(const void* __restrict__ dur_raw, int S) {
    __shared__ int s[S_CONST];
    __shared__ int red[S_CONST / 32];
    __shared__ int use64_sh;
    int b = blockIdx.x;
    int t = threadIdx.x;

    const long long* d64 = (const long long*)dur_raw;
    const int*       d32 = (const int*)dur_raw;

    // Dtype detect from the first 512 int64 words ONLY (4 KB: in-bounds under
    // both int32 and int64 interpretations). Durations lie in [0,8); int32
    // data read as int64 forms out-of-range value-pairs w.h.p. Deterministic.
    int ok = 1;
    if (t < 512) {
        long long v = d64[t];
        ok = (v >= 0 && v < 8) ? 1 : 0;
    }
    unsigned ballot = __ballot_sync(0xffffffffu, ok);
    if ((t & 31) == 0) red[t >> 5] = (ballot == 0xffffffffu) ? 1 : 0;
    __syncthreads();
    if (t == 0) {
        int all = 1;
        #pragma unroll
        for (int i = 0; i < (512 / 32); i++) all &= red[i];
        use64_sh = all;
    }
    __syncthreads();

    s[t] = use64_sh ? (int)d64[(long long)b * S + t]
                    : d32[(long long)b * S + t];
    __syncthreads();
    // Hillis-Steele inclusive scan
    #pragma unroll
    for (int off = 1; off < S_CONST; off <<= 1) {
        int v = (t >= off) ? s[t - off] : 0;
        __syncthreads();
        s[t] += v;
        __syncthreads();
    }
    g_cum[b * S + t] = s[t];
    if (t == S - 1) g_mel[b] = s[t];
}

// One output row (256 floats = 64 float4) per 64 consecutive threads.
// Warp lane 0 does the binary search; result broadcast via shfl.
__global__ void fill_kernel(const float* __restrict__ x,
                            float* __restrict__ out,
                            float* __restrict__ mask,
                            int S, int max_mel, long long n_rows) {
    long long gid = (long long)blockIdx.x * blockDim.x + threadIdx.x;
    long long row = gid >> 6;
    int lane64 = (int)(gid & 63);
    if (row >= n_rows) return;

    int b = (int)(row / max_mel);
    int t = (int)(row - (long long)b * max_mel);
    int ml = g_mel[b];

    float4* out4 = reinterpret_cast<float4*>(out) + row * 64;

    if (t >= ml) {
        out4[lane64] = make_float4(0.f, 0.f, 0.f, 0.f);
        if (lane64 == 0) mask[row] = 1.0f;
    } else {
        int idx = 0;
        if ((threadIdx.x & 31) == 0) {
            // searchsorted(cum, t, side='right'): first i with cum[i] > t
            const int* cum = g_cum + b * S;
            int lo = 0, hi = S;
            while (lo < hi) {
                int mid = (lo + hi) >> 1;
                if (cum[mid] <= t) lo = mid + 1;
                else hi = mid;
            }
            idx = lo < S - 1 ? lo : S - 1;
        }
        idx = __shfl_sync(0xffffffffu, idx, 0);
        const float4* src = reinterpret_cast<const float4*>(x)
                            + ((long long)b * S + idx) * 64;
        out4[lane64] = src[lane64];
        if (lane64 == 0) mask[row] = 0.0f;
    }
}

extern "C" void kernel_launch(void* const* d_in, const int* in_sizes, int n_in,
                              void* d_out, int out_size) {
    const float* x = (const float*)d_in[0];

    const int B = B_CONST;
    const int E = in_sizes[0] / in_sizes[1];     // 256
    const int S = in_sizes[1] / B;               // 1024
    const int max_mel = out_size / (B * (E + 1));

    float* out = (float*)d_out;
    float* mask = out + (long long)B * max_mel * E;

    cumsum_kernel<<<B, S_CONST>>>(d_in[1], S);

    long long n_rows = (long long)B * max_mel;
    long long n_threads = n_rows * 64;
    int block = 256;
    long long grid = (n_threads + block - 1) / block;
    fill_kernel<<<(unsigned)grid, block>>>(x, out, mask, S, max_mel, n_rows);
}

// round 7
// speedup vs baseline: 1.6753x; 1.6753x over previous
#include <cuda_runtime.h>
#include <cuda_bf16.h>

// LengthRegulator: expand x[b,s,:] by duration[b,s] along time, then mask.
// out layout: [B*max_mel*E] floats, then [B*max_mel] mask floats (0.0/1.0).

#define B_CONST 32
#define S_CONST 1024
#define MAX_MEL_CAP (S_CONST * 8)   // duration < 8

__device__ int g_cum[B_CONST * S_CONST];
__device__ int g_mel[B_CONST];
__device__ int g_idx[B_CONST * MAX_MEL_CAP];

__global__ void cumsum_kernel(const void* __restrict__ dur_raw, int S) {
    __shared__ int s[S_CONST];
    __shared__ int red[S_CONST / 32];
    __shared__ int use64_sh;
    int b = blockIdx.x;
    int t = threadIdx.x;

    const long long* d64 = (const long long*)dur_raw;
    const int*       d32 = (const int*)dur_raw;

    // Dtype detect from first 512 int64 words only (in-bounds either way).
    // Durations lie in [0,8); int32 data read as int64 is out-of-range w.h.p.
    int ok = 1;
    if (t < 512) {
        long long v = d64[t];
        ok = (v >= 0 && v < 8) ? 1 : 0;
    }
    unsigned ballot = __ballot_sync(0xffffffffu, ok);
    if ((t & 31) == 0) red[t >> 5] = (ballot == 0xffffffffu) ? 1 : 0;
    __syncthreads();
    if (t == 0) {
        int all = 1;
        #pragma unroll
        for (int i = 0; i < (512 / 32); i++) all &= red[i];
        use64_sh = all;
    }
    __syncthreads();

    s[t] = use64_sh ? (int)d64[b * S + t] : d32[b * S + t];
    __syncthreads();
    #pragma unroll
    for (int off = 1; off < S_CONST; off <<= 1) {
        int v = (t >= off) ? s[t - off] : 0;
        __syncthreads();
        s[t] += v;
        __syncthreads();
    }
    g_cum[b * S + t] = s[t];
    if (t == S - 1) g_mel[b] = s[t];
}

// Invert the cumsum into a direct index map: g_idx[b][t] = source position s
// for t in [cum[s-1], cum[s]); -1 sentinel for the masked tail.
__global__ void build_idx_kernel(int S, int max_mel) {
    int b = blockIdx.x;
    int t = threadIdx.x;       // == s
    int c1 = g_cum[b * S + t];
    int c0 = (t == 0) ? 0 : g_cum[b * S + t - 1];
    int* idx = g_idx + b * max_mel;
    for (int j = c0; j < c1; j++) idx[j] = t;
    // tail fill
    int ml = g_mel[b];
    for (int j = ml + t; j < max_mel; j += S_CONST) idx[j] = -1;
}

// 4 output rows per 256-thread block; 64 lanes stream one row (64 float4).
// blockIdx.y = batch (no 64-bit division anywhere). All int32 addressing.
__global__ void fill_kernel(const float* __restrict__ x,
                            float* __restrict__ out,
                            float* __restrict__ mask,
                            int S, int max_mel) {
    int t = blockIdx.x * 4 + (threadIdx.x >> 6);
    if (t >= max_mel) return;
    int lane = threadIdx.x & 63;
    int b = blockIdx.y;

    int row = b * max_mel + t;               // < 229376
    int s = __ldg(g_idx + row);

    float4* out4 = reinterpret_cast<float4*>(out) + row * 64;
    if (s < 0) {
        out4[lane] = make_float4(0.f, 0.f, 0.f, 0.f);
        if (lane == 0) mask[row] = 1.0f;
    } else {
        const float4* src = reinterpret_cast<const float4*>(x)
                            + (b * S + s) * 64;
        out4[lane] = src[lane];
        if (lane == 0) mask[row] = 0.0f;
    }
}

extern "C" void kernel_launch(void* const* d_in, const int* in_sizes, int n_in,
                              void* d_out, int out_size) {
    const float* x = (const float*)d_in[0];

    const int B = B_CONST;
    const int E = in_sizes[0] / in_sizes[1];     // 256
    const int S = in_sizes[1] / B;               // 1024
    const int max_mel = out_size / (B * (E + 1));

    float* out = (float*)d_out;
    float* mask = out + (long long)B * max_mel * E;

    cumsum_kernel<<<B, S_CONST>>>(d_in[1], S);
    build_idx_kernel<<<B, S_CONST>>>(S, max_mel);

    dim3 grid((max_mel + 3) / 4, B);
    fill_kernel<<<grid, 256>>>(x, out, mask, S, max_mel);
}